// round 8
// baseline (speedup 1.0000x reference)
#include <cuda_runtime.h>
#include <cuda_fp16.h>
#include <cstdint>
#include <cstddef>

// ====================== problem constants ======================
#define HW     1024
#define NCONV  1024          // 512 active blocks * 2 half-blocks (16 rows x 32 cols)
#define NTOT   2048          // + 1024 zero-fill block items

// ====================== smem layout (32-bit words) =============
#define S_SCALE_W 0
#define S_BIAS_W  64
#define S_STG_W   128                 // f32 stage: 18*34 px * 32 ch = 19584 words
#define S_F0_W    19712               // fp16 half: 18*34 px * 16 words = 9792
#define S_F1_W    29504
#define S_WP_W    39296               // fp16 weights: 9216 uint2 = 18432 words
#define S_TOTAL_B 230912              // 57728 words * 4B

// ====================== helpers ================================
__device__ __forceinline__ void mma16(float* c,
                                      uint32_t a0, uint32_t a1, uint32_t a2, uint32_t a3,
                                      uint32_t b0, uint32_t b1) {
    asm volatile(
        "mma.sync.aligned.m16n8k16.row.col.f32.f16.f16.f32 "
        "{%0,%1,%2,%3}, {%4,%5,%6,%7}, {%8,%9}, {%0,%1,%2,%3};"
        : "+f"(c[0]), "+f"(c[1]), "+f"(c[2]), "+f"(c[3])
        : "r"(a0), "r"(a1), "r"(a2), "r"(a3), "r"(b0), "r"(b1));
}

__device__ __forceinline__ uint32_t pack_h2(float lo, float hi) {
    __half2 h = __floats2half2_rn(lo, hi);
    return *(uint32_t*)&h;
}

__device__ __forceinline__ void cp_async16(uint32_t dst_smem, const void* src, int src_sz) {
    asm volatile("cp.async.cg.shared.global [%0], [%1], 16, %2;"
                 :: "r"(dst_smem), "l"(src), "r"(src_sz) : "memory");
}
__device__ __forceinline__ void cp_commit() {
    asm volatile("cp.async.commit_group;" ::: "memory");
}
__device__ __forceinline__ void cp_wait0() {
    asm volatile("cp.async.wait_group 0;" ::: "memory");
}

// Issue cp.async of ci-half h (channels 32h..32h+31) of the 18x34 patch around
// (gr0-1, gc0-1) into the LINEAR f32 stage buffer (byte address stgb).
// 18*34 px * 8 float4 = 4896 transfers over 512 threads.
__device__ __forceinline__ void issue_half(const float* __restrict__ inp,
                                           int gr0, int gc0, int h,
                                           uint32_t stgb, int tid) {
    #pragma unroll
    for (int u = 0; u < 10; u++) {
        int f = tid + u * 512;
        if (u < 9 || tid < 288) {
            int px = f >> 3, c8 = f & 7;
            int prow = px / 34;
            int pcol = px - prow * 34;
            int ir = gr0 - 1 + prow, ic = gc0 - 1 + pcol;
            int ok = ((unsigned)ir < (unsigned)HW) & ((unsigned)ic < (unsigned)HW);
            const float* src = inp + ((size_t)(ir & 1023) * HW + (ic & 1023)) * 64
                               + h * 32 + c8 * 4;
            cp_async16(stgb + f * 16, src, ok ? 16 : 0);
        }
    }
}

// Convert staged f32 half -> fp16 half. Swizzle cw ^= ((pcol>>1)&3)<<2.
// fp16 layout: word = px*16 + cw, word = half2(ch 2cw, ch 2cw+1).
__device__ __forceinline__ void convert_half(const float* __restrict__ stg,
                                             uint32_t* __restrict__ dst, int tid) {
    #pragma unroll
    for (int u = 0; u < 10; u++) {
        int f = tid + u * 512;
        if (u < 9 || tid < 288) {
            float4 v = ((const float4*)stg)[f];
            int px = f >> 3, c8 = f & 7;
            int pcol = px % 34;
            int swz = ((pcol >> 1) & 3) << 2;
            uint2 o;
            o.x = pack_h2(v.x, v.y);
            o.y = pack_h2(v.z, v.w);
            *(uint2*)(dst + px * 16 + ((c8 * 2) ^ swz)) = o;
        }
    }
}

// One k16 mma step: tap SS (0..8), 16-ch group CIG (0/1) within the half.
// Warp tile: 1 px row x 32 px cols (32 m) x 64 n.  mf = col-half (0..15 / 16..31).
#define KSTEP16(SS, CIG, BF, PW)                                            \
{                                                                           \
    const int kh_ = ((SS) >= 6) ? 2 : (((SS) >= 3) ? 1 : 0);                \
    const int kw_ = (SS) - kh_ * 3;                                         \
    _Pragma("unroll")                                                       \
    for (int mf = 0; mf < 2; mf++) {                                        \
        const int pc_ = grp + kw_ + (mf << 4);                              \
        const int swz_ = ((pc_ >> 1) & 3) << 2;                             \
        const int e0 = (((CIG) << 3) + q) ^ swz_;                           \
        const int e2 = e0 ^ 4;                                              \
        const int ba = ((rb + kh_) * 34 + pc_) << 4;                        \
        uint32_t a0 = (PW)[ba + e0];                                        \
        uint32_t a1 = (PW)[ba + 128 + e0];                                  \
        uint32_t a2 = (PW)[ba + e2];                                        \
        uint32_t a3 = (PW)[ba + 128 + e2];                                  \
        _Pragma("unroll")                                                   \
        for (int nf = 0; nf < 8; nf++)                                      \
            mma16(acc[mf][nf], a0, a1, a2, a3, BF[nf].x, BF[nf].y);         \
    }                                                                       \
}

// 18 k16-steps of one ci-half (H = 0/1). Weight step t = tap*4 + H*2 + cig.
#define COMPUTE_HALF16(FW, H)                                               \
{                                                                           \
    const uint32_t* pw = (const uint32_t*)(sm + (FW));                      \
    const int tb0 = (H) * 2;                                                \
    uint2 bfa[8], bfb[8];                                                   \
    _Pragma("unroll")                                                       \
    for (int nf = 0; nf < 8; nf++)                                          \
        bfa[nf] = bp2[(tb0 * 64 + nf * 8 + grp) * 4 + q];                   \
    _Pragma("unroll 1")                                                     \
    for (int ss = 0; ss < 9; ss++) {                                        \
        const int tA = ss * 4 + tb0;                                        \
        _Pragma("unroll")                                                   \
        for (int nf = 0; nf < 8; nf++)                                      \
            bfb[nf] = bp2[((tA + 1) * 64 + nf * 8 + grp) * 4 + q];          \
        KSTEP16(ss, 0, bfa, pw);                                            \
        const int tn = (ss < 8) ? (tA + 4) : tb0;                           \
        _Pragma("unroll")                                                   \
        for (int nf = 0; nf < 8; nf++)                                      \
            bfa[nf] = bp2[(tn * 64 + nf * 8 + grp) * 4 + q];                \
        KSTEP16(ss, 1, bfb, pw);                                            \
    }                                                                       \
}

// ====================== single fused persistent kernel =========
// 148 CTAs x 512 threads (16 warps, 4/SMSP), 1 CTA/SM. fp16 mma, f32 accum.
// Item = half-block: M=512 (16 px rows x 32 cols), N=64, K=576.
// Warp w handles px row gr0+w, all 32 cols, all 64 n.
__global__ void __launch_bounds__(512, 1)
convk(const float* __restrict__ inp,  const float* __restrict__ w,
      const float* __restrict__ cb,   const float* __restrict__ gm,
      const float* __restrict__ bt,   const float* __restrict__ mn,
      const float* __restrict__ vr,   const int* __restrict__ abi,
      float* __restrict__ out) {
    extern __shared__ float sm[];
    const int tid  = threadIdx.x;
    const int wid  = tid >> 5;
    const int lane = tid & 31;
    const int grp  = lane >> 2;      // 0..7
    const int q    = lane & 3;       // 0..3

    uint32_t smem_u32;
    asm("{ .reg .u64 t; cvta.to.shared.u64 t, %1; cvt.u32.u64 %0, t; }"
        : "=r"(smem_u32) : "l"((const void*)sm));
    const uint32_t stg_u32 = smem_u32 + S_STG_W * 4;

    // ---- per-CTA prep: fp16 weight fragments + fused scale/bias ----
    {
        uint2* wsm = (uint2*)(sm + S_WP_W);
        #pragma unroll 2
        for (int idx = tid; idx < 9216; idx += 512) {
            int qq = idx & 3;
            int n  = (idx >> 2) & 63;
            int t  = idx >> 8;
            int k0 = 16 * t + 2 * qq;
            uint2 o;
            o.x = pack_h2(w[k0 * 64 + n],       w[(k0 + 1) * 64 + n]);
            o.y = pack_h2(w[(k0 + 8) * 64 + n], w[(k0 + 9) * 64 + n]);
            wsm[idx] = o;
        }
        if (tid < 64) {
            float s = gm[tid] * rsqrtf(vr[tid] + 1e-3f);
            sm[S_SCALE_W + tid] = s;
            sm[S_BIAS_W + tid]  = cb[tid] * s + bt[tid] - mn[tid] * s;
        }
    }

    const int rb = wid;                  // warp's pixel row (0..15)
    const uint2* bp2 = (const uint2*)(sm + S_WP_W);

    // ---- prologue: start loading first item's half0 ----
    int gr0, gc0;
    {
        const int it0 = blockIdx.x;      // always < NCONV (148 < 1024)
        const int b = it0 >> 1, sub = it0 & 1;
        gr0 = abi[3 * b + 1] * 32 + sub * 16;
        gc0 = abi[3 * b + 2] * 32;
        issue_half(inp, gr0, gc0, 0, stg_u32, tid);
        cp_commit();
    }

    for (int it = blockIdx.x; it < NTOT; it += gridDim.x) {
        if (it < NCONV) {
            // ---- h0 staged -> convert; then start h1 into stage ----
            cp_wait0();
            __syncthreads();
            convert_half(sm + S_STG_W, (uint32_t*)(sm + S_F0_W), tid);
            __syncthreads();             // all convert reads of stage done
            issue_half(inp, gr0, gc0, 1, stg_u32, tid);
            cp_commit();

            float acc[2][8][4];
            #pragma unroll
            for (int a = 0; a < 2; a++)
                #pragma unroll
                for (int c = 0; c < 8; c++)
                    #pragma unroll
                    for (int d = 0; d < 4; d++) acc[a][c][d] = 0.f;

            COMPUTE_HALF16(S_F0_W, 0)    // overlaps h1 load

            // ---- h1 staged -> convert; then start next item's h0 ----
            cp_wait0();
            __syncthreads();
            convert_half(sm + S_STG_W, (uint32_t*)(sm + S_F1_W), tid);
            __syncthreads();

            const int itn = it + gridDim.x;
            int grn = 0, gcn = 0;
            if (itn < NCONV) {
                const int b = itn >> 1, sub = itn & 1;
                grn = abi[3 * b + 1] * 32 + sub * 16;
                gcn = abi[3 * b + 2] * 32;
                issue_half(inp, grn, gcn, 0, stg_u32, tid);
            }
            cp_commit();

            COMPUTE_HALF16(S_F1_W, 1)    // overlaps next h0 load

            // ---- epilogue: fused BN scale/bias + ReLU ----
            const int gpr = gr0 + rb;
            #pragma unroll
            for (int mf = 0; mf < 2; mf++) {
                const int gpc = gc0 + (mf << 4) + grp;
                #pragma unroll
                for (int nf = 0; nf < 8; nf++) {
                    const int n0 = nf * 8 + 2 * q;
                    const float s0 = sm[S_SCALE_W + n0], s1 = sm[S_SCALE_W + n0 + 1];
                    const float d0 = sm[S_BIAS_W + n0],  d1 = sm[S_BIAS_W + n0 + 1];
                    float* p0 = out + ((size_t)gpr * HW + gpc) * 64 + n0;
                    float2 v0, v1;
                    v0.x = fmaxf(fmaf(acc[mf][nf][0], s0, d0), 0.f);
                    v0.y = fmaxf(fmaf(acc[mf][nf][1], s1, d1), 0.f);
                    v1.x = fmaxf(fmaf(acc[mf][nf][2], s0, d0), 0.f);
                    v1.y = fmaxf(fmaf(acc[mf][nf][3], s1, d1), 0.f);
                    __stcs((float2*)p0, v0);
                    __stcs((float2*)(p0 + 8 * 64), v1);    // px col gpc+8
                }
            }
            gr0 = grn; gc0 = gcn;
        } else {
            // ================= zero-fill item =================
            const int blk = it - NCONV;
            int lo = 0, hi = 511, found = 0;
            while (lo <= hi) {
                int mid = (lo + hi) >> 1;
                int f = abi[3 * mid + 1] * 32 + abi[3 * mid + 2];
                if (f == blk) { found = 1; break; }
                if (f < blk) lo = mid + 1; else hi = mid - 1;
            }
            if (!found) {
                const int bi = blk >> 5, bj = blk & 31;
                const float4 z = make_float4(0.f, 0.f, 0.f, 0.f);
                #pragma unroll 8
                for (int j = 0; j < 32; j++) {
                    int idx = tid + j * 512;          // 0..16383 float4s
                    int r   = idx >> 9;               // 512 float4 per pixel row
                    int c4  = idx & 511;
                    __stcs((float4*)(out + ((size_t)(bi * 32 + r) * HW + bj * 32) * 64) + c4, z);
                }
            }
        }
    }
    cp_wait0();                          // drain any in-flight cp.async
}

// ====================== launch =================================
extern "C" void kernel_launch(void* const* d_in, const int* in_sizes, int n_in,
                              void* d_out, int out_size) {
    const float* inp   = (const float*)d_in[0];
    const float* w     = (const float*)d_in[1];
    const float* cb    = (const float*)d_in[2];
    const float* gamma = (const float*)d_in[3];
    const float* beta  = (const float*)d_in[4];
    const float* mean  = (const float*)d_in[5];
    const float* var   = (const float*)d_in[6];
    const int*   abi   = (const int*)d_in[7];
    float* out = (float*)d_out;

    cudaFuncSetAttribute(convk, cudaFuncAttributeMaxDynamicSharedMemorySize, S_TOTAL_B);
    convk<<<148, 512, S_TOTAL_B>>>(inp, w, cb, gamma, beta, mean, var, abi, out);
}